// round 2
// baseline (speedup 1.0000x reference)
#include <cuda_runtime.h>
#include <cstddef>

// STPCell fused kernel for GB300 (sm_103a).
// Structure:
//   prep_kernel : per-(j,k) sigmoid constants -> __device__ scratch (once per call)
//   px_kernel   : pxb[j,b] = (p @ x)[j,b]
//   main_kernel : streams X,U once, fuses X_new/U_new/W construction with the
//                 k-contraction, finalizes h_new. HBM-bound by design.

#define HH  1024
#define IND 512
#define BB  32

__device__ float g_zx[HH * HH];   // z_x  = 0.001 + 0.099*sig(c_x)
__device__ float g_zu[HH * HH];   // z_u  = 0.001 + 0.099*sig(c_u)
__device__ float g_uc[HH * HH];   // Ucap = 0.9*sig(c_U)
__device__ float g_px[HH * BB];   // (p @ x)[j, b]

__device__ __forceinline__ float sigf(float v) {
    return 1.0f / (1.0f + __expf(-v));
}

// ---------------------------------------------------------------------------
// Precompute per-(j,k) sigmoid-derived constants (vectorized float4).
// ---------------------------------------------------------------------------
__global__ __launch_bounds__(256) void prep_kernel(
    const float* __restrict__ c_x,
    const float* __restrict__ c_u,
    const float* __restrict__ c_U)
{
    int i = blockIdx.x * blockDim.x + threadIdx.x;   // float4 index, HH*HH/4 total
    float4 a  = reinterpret_cast<const float4*>(c_x)[i];
    float4 bq = reinterpret_cast<const float4*>(c_u)[i];
    float4 c  = reinterpret_cast<const float4*>(c_U)[i];

    float4 zx, zu, uc;
    zx.x = 0.001f + 0.099f * sigf(a.x);
    zx.y = 0.001f + 0.099f * sigf(a.y);
    zx.z = 0.001f + 0.099f * sigf(a.z);
    zx.w = 0.001f + 0.099f * sigf(a.w);
    zu.x = 0.001f + 0.099f * sigf(bq.x);
    zu.y = 0.001f + 0.099f * sigf(bq.y);
    zu.z = 0.001f + 0.099f * sigf(bq.z);
    zu.w = 0.001f + 0.099f * sigf(bq.w);
    uc.x = 0.9f * sigf(c.x);
    uc.y = 0.9f * sigf(c.y);
    uc.z = 0.9f * sigf(c.z);
    uc.w = 0.9f * sigf(c.w);

    reinterpret_cast<float4*>(g_zx)[i] = zx;
    reinterpret_cast<float4*>(g_zu)[i] = zu;
    reinterpret_cast<float4*>(g_uc)[i] = uc;
}

// ---------------------------------------------------------------------------
// pxb[j,b] = sum_i p[j,i] * x[i,b].   p:(H,IN) row-major, x:(IN,B) row-major.
// One block per j, 256 threads: b = tid&31, segment = tid>>5 (8 segs x 64 i).
// ---------------------------------------------------------------------------
__global__ __launch_bounds__(256) void px_kernel(
    const float* __restrict__ p,
    const float* __restrict__ x)
{
    int j   = blockIdx.x;
    int tid = threadIdx.x;
    int b   = tid & 31;
    int seg = tid >> 5;

    const float* prow = p + j * IND;
    float acc = 0.0f;
    int i0 = seg * 64;
    #pragma unroll 8
    for (int i = i0; i < i0 + 64; ++i)
        acc = fmaf(prow[i], x[i * BB + b], acc);

    __shared__ float red[8][BB];
    red[seg][b] = acc;
    __syncthreads();

    if (tid < BB) {
        float s = 0.0f;
        #pragma unroll
        for (int wI = 0; wI < 8; ++wI) s += red[wI][tid];
        g_px[j * BB + tid] = s;
    }
}

// ---------------------------------------------------------------------------
// Main fused kernel: one CTA per j row (1024 CTAs, 256 threads).
// Thread t owns k = 4t..4t+3. Per-(j,k) constants live in registers across
// the whole batch loop; X/U/h are streamed with 1-deep software pipelining.
// ---------------------------------------------------------------------------
__global__ __launch_bounds__(256) void main_kernel(
    const float* __restrict__ h,
    const float* __restrict__ X,
    const float* __restrict__ U,
    const float* __restrict__ w,
    const float* __restrict__ c_h,
    const float* __restrict__ bias,
    float* __restrict__ out)
{
    const int j    = blockIdx.x;
    const int tid  = threadIdx.x;
    const int lane = tid & 31;
    const int warp = tid >> 5;

    const int rowP = j * (HH / 4) + tid;      // float4 index into (j, 4t..4t+3)

    // Per-(j,k) constants, resident in registers for the entire b loop.
    const float4 zx   = reinterpret_cast<const float4*>(g_zx)[rowP];
    const float4 zu   = reinterpret_cast<const float4*>(g_zu)[rowP];
    const float4 ucap = reinterpret_cast<const float4*>(g_uc)[rowP];
    const float4 wv   = reinterpret_cast<const float4*>(w)[rowP];

    __shared__ float red[8][BB];

    // Software-pipelined streaming of X, U, h over batches.
    float4 xv = reinterpret_cast<const float4*>(X)[j * (HH / 4) + tid];   // b=0
    float4 uv = reinterpret_cast<const float4*>(U)[j * (HH / 4) + tid];
    float4 hv = reinterpret_cast<const float4*>(h)[tid];
    float  hj = __ldg(h + j);

    #pragma unroll 1
    for (int b = 0; b < BB; ++b) {
        const int bn = (b + 1 < BB) ? (b + 1) : (BB - 1);
        const int rowN = (bn * HH + j) * (HH / 4) + tid;
        float4 xnx = reinterpret_cast<const float4*>(X)[rowN];
        float4 unx = reinterpret_cast<const float4*>(U)[rowN];
        float4 hnx = reinterpret_cast<const float4*>(h)[bn * (HH / 4) + tid];
        float  hjn = __ldg(h + bn * HH + j);

        float acc = 0.0f;
        // X_new = z_x + (1-z_x)*X - U*(X*hj)
        //       = fma(z_x, 1-X, X) - U*(X*hj)
        // U_new = Ucap*(z_u + hj) + U*((1-z_u) - Ucap*hj), clipped to [Ucap, 1]
        // acc  += w * U_new * X_new * h[b,k]
        #define STP_PROC(C)                                                 \
        {                                                                   \
            float xx = xv.C, uu = uv.C;                                     \
            float xnew = fmaf(zx.C, 1.0f - xx, xx);                         \
            xnew = fmaf(-uu, xx * hj, xnew);                                \
            float addu = ucap.C * (zu.C + hj);                              \
            float cofu = fmaf(-ucap.C, hj, 1.0f - zu.C);                    \
            float unew = fmaf(uu, cofu, addu);                              \
            unew = fminf(fmaxf(unew, ucap.C), 1.0f);                        \
            acc  = fmaf(wv.C * unew * xnew, hv.C, acc);                     \
        }
        STP_PROC(x) STP_PROC(y) STP_PROC(z) STP_PROC(w)
        #undef STP_PROC

        // Warp tree-reduce the partial dot over this warp's 128 k values.
        #pragma unroll
        for (int o = 16; o > 0; o >>= 1)
            acc += __shfl_xor_sync(0xffffffffu, acc, o);
        if (lane == 0) red[warp][b] = acc;   // each warp owns its row: no race

        xv = xnx; uv = unx; hv = hnx; hj = hjn;
    }
    __syncthreads();

    // Finalize: threads 0..31 each handle one batch b for this j.
    if (tid < BB) {
        const int b = tid;
        float rec = 0.0f;
        #pragma unroll
        for (int wI = 0; wI < 8; ++wI) rec += red[wI][b];

        float pre = rec + g_px[j * BB + b] + bias[j];
        float zh  = 0.5f * sigf(c_h[j]);        // E_H = 0.5
        float hbj = h[b * HH + j];
        // (1-zh)*h + zh*sig(pre) = h + zh*(sig(pre) - h)
        out[b * HH + j] = fmaf(zh, sigf(pre) - hbj, hbj);
    }
}

// ---------------------------------------------------------------------------
// Launch. Input order (metadata): x, h, X, U, c_x, c_u, c_U, c_h, w, p, b
// Output: h_new as (B, H) fp32.
// ---------------------------------------------------------------------------
extern "C" void kernel_launch(void* const* d_in, const int* in_sizes, int n_in,
                              void* d_out, int out_size)
{
    const float* x_in = (const float*)d_in[0];
    const float* h    = (const float*)d_in[1];
    const float* X    = (const float*)d_in[2];
    const float* U    = (const float*)d_in[3];
    const float* c_x  = (const float*)d_in[4];
    const float* c_u  = (const float*)d_in[5];
    const float* c_U  = (const float*)d_in[6];
    const float* c_h  = (const float*)d_in[7];
    const float* w    = (const float*)d_in[8];
    const float* p    = (const float*)d_in[9];
    const float* bias = (const float*)d_in[10];
    float* out = (float*)d_out;

    prep_kernel<<<(HH * HH / 4) / 256, 256>>>(c_x, c_u, c_U);
    px_kernel<<<HH, 256>>>(p, x_in);
    main_kernel<<<HH, 256>>>(h, X, U, w, c_h, bias, out);
}

// round 3
// speedup vs baseline: 1.1023x; 1.1023x over previous
#include <cuda_runtime.h>
#include <cstddef>

// STPCell fully-fused single-kernel implementation for GB300 (sm_103a).
// One CTA per j row (1024 CTAs x 256 threads). Prologue computes (p@x)[j,:]
// and the per-(j,k) sigmoid constants in registers while the first X/U tile
// loads are in flight; the b-loop streams X,U exactly once (268 MB, the
// DRAM-bound floor) with 1-deep software pipelining.

#define HH  1024
#define IND 512
#define BB  32

__device__ __forceinline__ float sigf(float v) {
    return 1.0f / (1.0f + __expf(-v));
}

__global__ __launch_bounds__(256, 4) void stp_main(
    const float* __restrict__ x_in,   // (IN, B)
    const float* __restrict__ h,      // (B, H)
    const float* __restrict__ X,      // (B, H, H)
    const float* __restrict__ U,      // (B, H, H)
    const float* __restrict__ c_x,    // (H, H)
    const float* __restrict__ c_u,    // (H, H)
    const float* __restrict__ c_U,    // (H, H)
    const float* __restrict__ c_h,    // (H, 1)
    const float* __restrict__ w,      // (H, H)
    const float* __restrict__ p,      // (H, IN)
    const float* __restrict__ bias,   // (H, 1)
    float* __restrict__ out)          // (B, H)
{
    const int j    = blockIdx.x;
    const int tid  = threadIdx.x;
    const int lane = tid & 31;
    const int warp = tid >> 5;
    const int rowP = j * (HH / 4) + tid;     // float4 index of (j, 4t..4t+3)

    __shared__ float red[8][BB];
    __shared__ float px_s[BB];
    __shared__ float hj_s[BB];

    // ---- issue all prologue loads up front (overlap with px compute) ----
    const float4 cxv = reinterpret_cast<const float4*>(c_x)[rowP];
    const float4 cuv = reinterpret_cast<const float4*>(c_u)[rowP];
    const float4 cUv = reinterpret_cast<const float4*>(c_U)[rowP];
    const float4 wv  = reinterpret_cast<const float4*>(w)[rowP];

    float4 xv = reinterpret_cast<const float4*>(X)[rowP];   // b = 0 tile
    float4 uv = reinterpret_cast<const float4*>(U)[rowP];
    float4 hv = reinterpret_cast<const float4*>(h)[tid];

    if (tid < BB) hj_s[tid] = h[tid * HH + j];              // hj for all b

    // ---- (p @ x)[j, b]: 8 segments of 64 i, b = lane ----
    {
        const int b   = tid & 31;
        const int seg = tid >> 5;
        const float* prow = p + j * IND;
        float acc = 0.0f;
        #pragma unroll 8
        for (int i = seg * 64; i < seg * 64 + 64; ++i)
            acc = fmaf(prow[i], x_in[i * BB + b], acc);
        red[seg][b] = acc;
    }
    __syncthreads();
    if (tid < BB) {
        float s = 0.0f;
        #pragma unroll
        for (int q = 0; q < 8; ++q) s += red[q][tid];
        px_s[tid] = s;
    }
    __syncthreads();   // red[] free for the b-loop; px_s/hj_s published

    // ---- per-(j,k) sigmoid constants, once, in registers ----
    float4 zx, zu, uc;
    zx.x = 0.001f + 0.099f * sigf(cxv.x);
    zx.y = 0.001f + 0.099f * sigf(cxv.y);
    zx.z = 0.001f + 0.099f * sigf(cxv.z);
    zx.w = 0.001f + 0.099f * sigf(cxv.w);
    zu.x = 0.001f + 0.099f * sigf(cuv.x);
    zu.y = 0.001f + 0.099f * sigf(cuv.y);
    zu.z = 0.001f + 0.099f * sigf(cuv.z);
    zu.w = 0.001f + 0.099f * sigf(cuv.w);
    uc.x = 0.9f * sigf(cUv.x);
    uc.y = 0.9f * sigf(cUv.y);
    uc.z = 0.9f * sigf(cUv.z);
    uc.w = 0.9f * sigf(cUv.w);

    // ---- streaming b-loop, 1-deep software pipeline ----
    #pragma unroll 1
    for (int b = 0; b < BB; ++b) {
        const int bn   = (b + 1 < BB) ? (b + 1) : (BB - 1);
        const int rowN = (bn * HH + j) * (HH / 4) + tid;
        float4 xnx = reinterpret_cast<const float4*>(X)[rowN];
        float4 unx = reinterpret_cast<const float4*>(U)[rowN];
        float4 hnx = reinterpret_cast<const float4*>(h)[bn * (HH / 4) + tid];

        const float hj = hj_s[b];
        float acc = 0.0f;

        // X_new = fma(z_x, 1-X, X) - U*(X*hj)
        // U_new = Ucap*(z_u + hj) + U*((1-z_u) - Ucap*hj), clipped [Ucap, 1]
        // acc  += (w * U_new * X_new) * h[b,k]
        #define STP_PROC(C)                                                 \
        {                                                                   \
            float xx = xv.C, uu = uv.C;                                     \
            float xnew = fmaf(zx.C, 1.0f - xx, xx);                         \
            xnew = fmaf(-uu, xx * hj, xnew);                                \
            float addu = uc.C * (zu.C + hj);                                \
            float cofu = fmaf(-uc.C, hj, 1.0f - zu.C);                      \
            float unew = fmaf(uu, cofu, addu);                              \
            unew = fminf(fmaxf(unew, uc.C), 1.0f);                         \
            acc  = fmaf(wv.C * unew * xnew, hv.C, acc);                     \
        }
        STP_PROC(x) STP_PROC(y) STP_PROC(z) STP_PROC(w)
        #undef STP_PROC

        // warp tree-reduce over this warp's 128 k values
        #pragma unroll
        for (int o = 16; o > 0; o >>= 1)
            acc += __shfl_xor_sync(0xffffffffu, acc, o);
        if (lane == 0) red[warp][b] = acc;     // warp owns its row: no race

        xv = xnx; uv = unx; hv = hnx;
    }
    __syncthreads();

    // ---- finalize: thread b (< 32) writes out[b, j] ----
    if (tid < BB) {
        const int b = tid;
        float rec = 0.0f;
        #pragma unroll
        for (int q = 0; q < 8; ++q) rec += red[q][b];

        float pre = rec + px_s[b] + bias[j];
        float zh  = 0.5f * sigf(c_h[j]);               // E_H = 0.5
        float hbj = h[b * HH + j];
        out[b * HH + j] = fmaf(zh, sigf(pre) - hbj, hbj);
    }
}

// ---------------------------------------------------------------------------
// Inputs (metadata order): x, h, X, U, c_x, c_u, c_U, c_h, w, p, b
// ---------------------------------------------------------------------------
extern "C" void kernel_launch(void* const* d_in, const int* in_sizes, int n_in,
                              void* d_out, int out_size)
{
    const float* x_in = (const float*)d_in[0];
    const float* h    = (const float*)d_in[1];
    const float* X    = (const float*)d_in[2];
    const float* U    = (const float*)d_in[3];
    const float* c_x  = (const float*)d_in[4];
    const float* c_u  = (const float*)d_in[5];
    const float* c_U  = (const float*)d_in[6];
    const float* c_h  = (const float*)d_in[7];
    const float* w    = (const float*)d_in[8];
    const float* p    = (const float*)d_in[9];
    const float* bias = (const float*)d_in[10];
    float* out = (float*)d_out;

    stp_main<<<HH, 256>>>(x_in, h, X, U, c_x, c_u, c_U, c_h, w, p, bias, out);
}